// round 1
// baseline (speedup 1.0000x reference)
#include <cuda_runtime.h>
#include <cstdint>
#include <cstddef>

#define DIM   8192
#define BATCH 8
#define TOPK  60

// ---------------- scratch (device globals; no allocation allowed) ----------
__device__ float g_act1[BATCH * DIM];
__device__ float g_act2[BATCH * DIM];
__device__ float g_vals[BATCH * 64];
__device__ int   g_idx [BATCH * 64];

typedef unsigned long long u64;

__device__ __forceinline__ void fma2(u64& d, u64 a, u64 b) {
    asm volatile("fma.rn.f32x2 %0, %1, %2, %0;" : "+l"(d) : "l"(a), "l"(b));
}
__device__ __forceinline__ float sigmoidf_(float x) {
    return 1.0f / (1.0f + __expf(-x));
}

// ---------------------------------------------------------------------------
// GEMM1: out[b][j] = sigmoid( sum_i sdr[b][i] * syn[j][i] )   (dense, fp32)
// Block = 128 threads (4 warps). Each warp owns 4 consecutive j rows.
// Block covers 16 rows; grid = DIM/16 = 512 blocks.
// sdr chunk (8 x 128 floats) staged in SMEM each iteration; synapse streamed
// from DRAM with 16B loads. Accumulate with packed f32x2 FMA (pairs over i).
// ---------------------------------------------------------------------------
__global__ __launch_bounds__(128) void gemm1_kernel(
    const float* __restrict__ sdr,
    const float* __restrict__ syn,
    float* __restrict__ out)
{
    __shared__ ulonglong2 s_sdr[BATCH][32];   // 8 x 128 floats = 4 KB

    const int tid  = threadIdx.x;
    const int warp = tid >> 5;
    const int lane = tid & 31;
    const int jBase = blockIdx.x * 16 + warp * 4;

    const ulonglong2* __restrict__ sdr2 = reinterpret_cast<const ulonglong2*>(sdr);
    const ulonglong2* __restrict__ syn2 = reinterpret_cast<const ulonglong2*>(syn);
    const int ROWU = DIM / 4;                 // 16B units per row = 2048

    u64 acc[BATCH][4];
#pragma unroll
    for (int b = 0; b < BATCH; ++b)
#pragma unroll
        for (int r = 0; r < 4; ++r) acc[b][r] = 0ull;

    for (int it = 0; it < DIM / 128; ++it) {
        __syncthreads();
        // cooperative load of sdr chunk: 8*32 = 256 ulonglong2, 128 threads
#pragma unroll
        for (int u = 0; u < 2; ++u) {
            int e = tid + u * 128;            // 0..255
            int b = e >> 5, c = e & 31;
            s_sdr[b][c] = sdr2[(size_t)b * ROWU + it * 32 + c];
        }
        __syncthreads();

        ulonglong2 w[4];
#pragma unroll
        for (int r = 0; r < 4; ++r)
            w[r] = syn2[(size_t)(jBase + r) * ROWU + it * 32 + lane];

#pragma unroll
        for (int b = 0; b < BATCH; ++b) {
            ulonglong2 s = s_sdr[b][lane];
#pragma unroll
            for (int r = 0; r < 4; ++r) {
                fma2(acc[b][r], s.x, w[r].x);
                fma2(acc[b][r], s.y, w[r].y);
            }
        }
    }

    // horizontal reduce: pair-sum + warp butterfly; lane (b*4+r) writes
#pragma unroll
    for (int b = 0; b < BATCH; ++b) {
#pragma unroll
        for (int r = 0; r < 4; ++r) {
            float lo = __uint_as_float((unsigned)(acc[b][r] & 0xffffffffull));
            float hi = __uint_as_float((unsigned)(acc[b][r] >> 32));
            float s = lo + hi;
#pragma unroll
            for (int o = 16; o > 0; o >>= 1)
                s += __shfl_xor_sync(0xffffffffu, s, o);
            if (lane == b * 4 + r)
                out[(size_t)b * DIM + jBase + r] = sigmoidf_(s);
        }
    }
}

// ---------------------------------------------------------------------------
// Top-k select, exact. One block (1024 threads) per row. Keys = float bits
// (all values positive -> uint order == float order). Binary search for the
// k-th largest key; keep all > K plus (k - count_gt) elements == K.
// Writes compact (idx, val) lists and/or a dense zero-filled output.
// ---------------------------------------------------------------------------
__global__ __launch_bounds__(1024) void topk_kernel(
    const float* __restrict__ act,
    float* __restrict__ dense,     // may be nullptr
    float* __restrict__ vals,      // may be nullptr
    int*   __restrict__ idxs,      // may be nullptr
    int k)
{
    const int row = blockIdx.x;
    const int tid = threadIdx.x;
    const float* __restrict__ arow = act + (size_t)row * DIM;

    unsigned key[8];
#pragma unroll
    for (int u = 0; u < 8; ++u)
        key[u] = __float_as_uint(arow[tid + u * 1024]);

    __shared__ int wsum[32];
    __shared__ unsigned s_bcast;

    // block-wide count of keys >= T
    auto count_ge = [&](unsigned T) -> int {
        int c = 0;
#pragma unroll
        for (int u = 0; u < 8; ++u) c += (key[u] >= T);
#pragma unroll
        for (int o = 16; o > 0; o >>= 1)
            c += __shfl_xor_sync(0xffffffffu, c, o);
        if ((tid & 31) == 0) wsum[tid >> 5] = c;
        __syncthreads();
        if (tid < 32) {
            int v = wsum[tid];
#pragma unroll
            for (int o = 16; o > 0; o >>= 1)
                v += __shfl_xor_sync(0xffffffffu, v, o);
            if (tid == 0) s_bcast = (unsigned)v;
        }
        __syncthreads();
        return (int)s_bcast;
    };

    // find largest K with count_ge(K) >= k  -> K is the k-th largest key
    unsigned lo = 0u, hi = 0xffffffffu;
    while (lo < hi) {
        unsigned mid = (unsigned)(((unsigned long long)lo + hi + 1ull) >> 1);
        if (count_ge(mid) >= k) lo = mid; else hi = mid - 1;
    }
    const unsigned K = lo;
    const int cnt_gt = count_ge(K + 1u);   // strictly greater
    const int rem = k - cnt_gt;            // how many == K to keep

    __shared__ int s_pos, s_eq;
    if (tid == 0) { s_pos = 0; s_eq = 0; }
    __syncthreads();

#pragma unroll
    for (int u = 0; u < 8; ++u) {
        unsigned ky = key[u];
        int gi = tid + u * 1024;
        float o = 0.0f;
        if (ky > K) {
            int p = atomicAdd(&s_pos, 1);
            float v = __uint_as_float(ky);
            if (vals) { vals[row * 64 + p] = v; idxs[row * 64 + p] = gi; }
            o = v;
        } else if (ky == K) {
            int e = atomicAdd(&s_eq, 1);
            if (e < rem) {
                int p = atomicAdd(&s_pos, 1);
                float v = __uint_as_float(ky);
                if (vals) { vals[row * 64 + p] = v; idxs[row * 64 + p] = gi; }
                o = v;
            }
        }
        if (dense) dense[(size_t)row * DIM + gi] = o;
    }
}

// ---------------------------------------------------------------------------
// GEMM2 (sparse): out[b][j] = sigmoid( sum_s v[b][s] * syn[j][idx[b][s]] )
// Thread = (j lane, b). Block = 32 j x 8 b; grid = DIM/32 = 256 blocks.
// idx/val lists broadcast from SMEM; 60 gathered loads per thread, fully
// unrolled for MLP. Traffic: 8192*480 32B sectors ~= 126 MB (vs 256 MB dense).
// ---------------------------------------------------------------------------
__global__ __launch_bounds__(256) void gemm2_kernel(
    const float* __restrict__ syn,
    const float* __restrict__ vals,
    const int*   __restrict__ idxs,
    float* __restrict__ out)
{
    __shared__ float sv[BATCH][TOPK];
    __shared__ int   si[BATCH][TOPK];

    const int tx = threadIdx.x;   // 0..31 (j)
    const int b  = threadIdx.y;   // 0..7
    const int t  = b * 32 + tx;

    for (int u = t; u < BATCH * TOPK; u += 256) {
        int bb = u / TOPK, ss = u % TOPK;
        sv[bb][ss] = vals[bb * 64 + ss];
        si[bb][ss] = idxs[bb * 64 + ss];
    }
    __syncthreads();

    const int j = blockIdx.x * 32 + tx;
    const float* __restrict__ wrow = syn + (size_t)j * DIM;

    float acc = 0.0f;
#pragma unroll
    for (int s = 0; s < TOPK; ++s)
        acc += sv[b][s] * __ldg(wrow + si[b][s]);

    out[(size_t)b * DIM + j] = sigmoidf_(acc);
}

// ---------------------------------------------------------------------------
extern "C" void kernel_launch(void* const* d_in, const int* in_sizes, int n_in,
                              void* d_out, int out_size)
{
    const float* sdr = (const float*)d_in[0];
    const float* syn = (const float*)d_in[1];
    // steps=2, top_k=60 fixed by setup_inputs (hardcoded)

    float *act1, *act2, *vals;
    int *idx;
    cudaGetSymbolAddress((void**)&act1, g_act1);
    cudaGetSymbolAddress((void**)&act2, g_act2);
    cudaGetSymbolAddress((void**)&vals, g_vals);
    cudaGetSymbolAddress((void**)&idx,  g_idx);

    // step 1: dense GEMM + sigmoid
    gemm1_kernel<<<DIM / 16, 128>>>(sdr, syn, act1);
    // step 1: top-k -> sparse lists
    topk_kernel<<<BATCH, 1024>>>(act1, nullptr, vals, idx, TOPK);
    // step 2: sparse GEMM + sigmoid
    gemm2_kernel<<<DIM / 32, dim3(32, 8)>>>(syn, vals, idx, act2);
    // step 2: top-k -> dense output (zeros elsewhere)
    topk_kernel<<<BATCH, 1024>>>(act2, (float*)d_out, nullptr, nullptr, TOPK);
}

// round 3
// speedup vs baseline: 1.5286x; 1.5286x over previous
#include <cuda_runtime.h>
#include <cstdint>
#include <cstddef>

#define DIM   8192
#define BATCH 8
#define TOPK  60

// ---------------- scratch (device globals; no allocation allowed) ----------
__device__ float g_act1[BATCH * DIM];
__device__ float g_act2[BATCH * DIM];
__device__ float g_vals[BATCH * 64];
__device__ int   g_idx [BATCH * 64];

typedef unsigned long long u64;

__device__ __forceinline__ void fma2(u64& d, u64 a, u64 b) {
    asm volatile("fma.rn.f32x2 %0, %1, %2, %0;" : "+l"(d) : "l"(a), "l"(b));
}
__device__ __forceinline__ float sigmoidf_(float x) {
    return 1.0f / (1.0f + __expf(-x));
}
__device__ __forceinline__ float pairsum(u64 a) {
    return __uint_as_float((unsigned)(a & 0xffffffffull)) +
           __uint_as_float((unsigned)(a >> 32));
}

// ---------------------------------------------------------------------------
// GEMM1 (raw, no sigmoid): out[b][j] = sum_i sdr[b][i] * syn[j][i]
// Block = 256 threads (8 warps). Warp w owns 4 consecutive rows; block covers
// 32 rows. K dim split into 8 chunks of 1024; each chunk's sdr slice (8x1024
// floats = 32KB) staged once in SMEM, then a barrier-free inner loop streams
// the synapse rows with unrolled independent 16B loads. f32x2 packed FMA.
// grid = 8192/32 = 256 blocks.
// ---------------------------------------------------------------------------
__global__ __launch_bounds__(256, 2) void gemm1_kernel(
    const float* __restrict__ sdr,
    const float* __restrict__ syn,
    float* __restrict__ out)
{
    __shared__ float4 s_sdr[BATCH * 256];     // 8 x 1024 floats = 32 KB

    const int tid  = threadIdx.x;
    const int warp = tid >> 5;
    const int lane = tid & 31;
    const int jBase = blockIdx.x * 32 + warp * 4;

    const float4* __restrict__ sdr4 = reinterpret_cast<const float4*>(sdr);
    const float4* __restrict__ syn4 = reinterpret_cast<const float4*>(syn);
    const int ROW4 = DIM / 4;                 // 2048 float4 per row

    u64 acc[4][BATCH];
#pragma unroll
    for (int r = 0; r < 4; ++r)
#pragma unroll
        for (int b = 0; b < BATCH; ++b) acc[r][b] = 0ull;

    for (int c = 0; c < 8; ++c) {             // 8 chunks of 1024 floats
        __syncthreads();
        // stage sdr chunk: 8 b x 256 float4 = 2048 float4, 8 per thread
#pragma unroll
        for (int u = 0; u < 8; ++u) {
            int e = tid + u * 256;            // 0..2047
            int b = e >> 8, q = e & 255;
            s_sdr[b * 256 + q] = sdr4[(size_t)b * ROW4 + c * 256 + q];
        }
        __syncthreads();

#pragma unroll 2
        for (int it = 0; it < 8; ++it) {      // 256 float4 / 32 lanes
            const int pos = it * 32 + lane;
            float4 w[4];
#pragma unroll
            for (int r = 0; r < 4; ++r)
                w[r] = syn4[(size_t)(jBase + r) * ROW4 + c * 256 + pos];

#pragma unroll
            for (int b = 0; b < BATCH; ++b) {
                float4 s = s_sdr[b * 256 + pos];
                u64 sx = *reinterpret_cast<u64*>(&s.x);
                u64 sz = *reinterpret_cast<u64*>(&s.z);
#pragma unroll
                for (int r = 0; r < 4; ++r) {
                    fma2(acc[r][b], sx, *reinterpret_cast<u64*>(&w[r].x));
                    fma2(acc[r][b], sz, *reinterpret_cast<u64*>(&w[r].z));
                }
            }
        }
    }

    // reduce: 32 (r,b) pairs, butterfly each, writer lane = r*8+b
#pragma unroll
    for (int r = 0; r < 4; ++r) {
#pragma unroll
        for (int b = 0; b < BATCH; ++b) {
            float v = pairsum(acc[r][b]);
#pragma unroll
            for (int o = 16; o > 0; o >>= 1)
                v += __shfl_xor_sync(0xffffffffu, v, o);
            if (lane == r * 8 + b)
                out[(size_t)b * DIM + jBase + r] = v;
        }
    }
}

// ---------------------------------------------------------------------------
// Exact top-k via 4-pass radix select (8-bit digits, MSB first).
// One block (1024 threads) per row, keys register-resident (8/thread).
// Keys = order-preserving transform of float bits (handles negatives).
// Warp-private histograms kill atomic contention. Sigmoid applied on output
// (monotone, so selection on raw values == selection on sigmoid values).
// ---------------------------------------------------------------------------
__global__ __launch_bounds__(1024) void topk_kernel(
    const float* __restrict__ act,
    float* __restrict__ dense,     // may be nullptr (zero-filled top-k output)
    float* __restrict__ vals,      // may be nullptr (compact sigmoid'd values)
    int*   __restrict__ idxs)      // may be nullptr
{
    const int row  = blockIdx.x;
    const int tid  = threadIdx.x;
    const int warp = tid >> 5;
    const int lane = tid & 31;
    const float* __restrict__ arow = act + (size_t)row * DIM;

    unsigned key[8];
#pragma unroll
    for (int u = 0; u < 8; ++u) {
        unsigned b = __float_as_uint(arow[tid + u * 1024]);
        key[u] = b ^ (unsigned)(((int)b >> 31) | 0x80000000);
    }

    __shared__ int hist[32][256];            // warp-private, 32 KB
    __shared__ int s_digit, s_kk;

    unsigned prefix = 0;
    int kk = TOPK;

#pragma unroll
    for (int pass = 0; pass < 4; ++pass) {
        const int sh = 24 - pass * 8;
        // zero histograms
#pragma unroll
        for (int u = 0; u < 8; ++u)
            (&hist[0][0])[tid + u * 1024] = 0;
        __syncthreads();

#pragma unroll
        for (int u = 0; u < 8; ++u) {
            unsigned ky = key[u];
            bool cand = (pass == 0) || ((ky >> (sh + 8)) == prefix);
            if (cand) atomicAdd(&hist[warp][(ky >> sh) & 255], 1);
        }
        __syncthreads();

        // reduce 32 warp copies -> hist[0][bin]
        if (tid < 256) {
            int s = 0;
#pragma unroll
            for (int w = 0; w < 32; ++w) s += hist[w][tid];
            hist[0][tid] = s;
        }
        __syncthreads();

        // top-down scan: find digit d where cumulative count from bin 255 >= kk
        if (warp == 0) {
            const int base = 255 - lane * 8;
            int cnt[8]; int local = 0;
#pragma unroll
            for (int j = 0; j < 8; ++j) { cnt[j] = hist[0][base - j]; local += cnt[j]; }
            int incl = local;
#pragma unroll
            for (int o = 1; o < 32; o <<= 1) {
                int v = __shfl_up_sync(0xffffffffu, incl, o);
                if (lane >= o) incl += v;
            }
            const int excl = incl - local;
            if (excl < kk && kk <= incl) {     // exactly one lane
                int run = excl; int found = 0;
#pragma unroll
                for (int j = 0; j < 8; ++j) {
                    if (!found && run + cnt[j] >= kk) {
                        s_digit = base - j;
                        s_kk = kk - run;
                        found = 1;
                    }
                    run += cnt[j];
                }
            }
        }
        __syncthreads();
        prefix = (prefix << 8) | (unsigned)s_digit;
        kk = s_kk;
        __syncthreads();
    }

    const unsigned K = prefix;   // k-th largest transformed key (exact)
    const int rem = kk;          // how many keys == K to keep

    __shared__ int s_pos, s_eq;
    if (tid == 0) { s_pos = 0; s_eq = 0; }
    __syncthreads();

#pragma unroll
    for (int u = 0; u < 8; ++u) {
        const unsigned ky = key[u];
        const int gi = tid + u * 1024;
        bool sel = false;
        if (ky > K) sel = true;
        else if (ky == K) {
            int e = atomicAdd(&s_eq, 1);
            if (e < rem) sel = true;
        }
        float sv = 0.0f;
        if (sel) {
            unsigned b = (ky & 0x80000000u) ? (ky ^ 0x80000000u) : ~ky;
            sv = sigmoidf_(__uint_as_float(b));
            if (vals) {
                int p = atomicAdd(&s_pos, 1);
                vals[row * 64 + p] = sv;
                idxs[row * 64 + p] = gi;
            }
        }
        if (dense) dense[(size_t)row * DIM + gi] = sv;
    }
}

// ---------------------------------------------------------------------------
// GEMM2 (sparse, raw): out[b][j] = sum_s v[b][s] * syn[j][idx[b][s]]
// Thread = (j lane, b). Block = 32 j x 8 b; grid = 256 blocks.
// 60 independent gathered loads per thread. ~126 MB effective DRAM traffic.
// ---------------------------------------------------------------------------
__global__ __launch_bounds__(256) void gemm2_kernel(
    const float* __restrict__ syn,
    const float* __restrict__ vals,
    const int*   __restrict__ idxs,
    float* __restrict__ out)
{
    __shared__ float sv[BATCH][TOPK];
    __shared__ int   si[BATCH][TOPK];

    const int tx = threadIdx.x;   // 0..31 (j)
    const int b  = threadIdx.y;   // 0..7
    const int t  = b * 32 + tx;

    for (int u = t; u < BATCH * TOPK; u += 256) {
        int bb = u / TOPK, ss = u % TOPK;
        sv[bb][ss] = vals[bb * 64 + ss];
        si[bb][ss] = idxs[bb * 64 + ss];
    }
    __syncthreads();

    const int j = blockIdx.x * 32 + tx;
    const float* __restrict__ wrow = syn + (size_t)j * DIM;

    float acc = 0.0f;
#pragma unroll
    for (int s = 0; s < TOPK; ++s)
        acc += sv[b][s] * __ldg(wrow + si[b][s]);

    out[(size_t)b * DIM + j] = acc;
}

// ---------------------------------------------------------------------------
extern "C" void kernel_launch(void* const* d_in, const int* in_sizes, int n_in,
                              void* d_out, int out_size)
{
    const float* sdr = (const float*)d_in[0];
    const float* syn = (const float*)d_in[1];
    // steps=2, top_k=60 fixed by setup_inputs (hardcoded)

    float *act1, *act2, *vals;
    int *idx;
    cudaGetSymbolAddress((void**)&act1, g_act1);
    cudaGetSymbolAddress((void**)&act2, g_act2);
    cudaGetSymbolAddress((void**)&vals, g_vals);
    cudaGetSymbolAddress((void**)&idx,  g_idx);

    // step 1: dense GEMM (raw sums)
    gemm1_kernel<<<DIM / 32, 256>>>(sdr, syn, act1);
    // step 1: top-k -> compact sigmoid'd lists
    topk_kernel<<<BATCH, 1024>>>(act1, nullptr, vals, idx);
    // step 2: sparse GEMM (raw sums)
    gemm2_kernel<<<DIM / 32, dim3(32, 8)>>>(syn, vals, idx, act2);
    // step 2: top-k -> dense sigmoid'd output (zeros elsewhere)
    topk_kernel<<<BATCH, 1024>>>(act2, (float*)d_out, nullptr, nullptr);
}